// round 3
// baseline (speedup 1.0000x reference)
#include <cuda_runtime.h>
#include <math.h>
#include <stdint.h>

#define NN 100000
#define RR 3
#define EE 320000
#define HIDD 128
#define HH 4
#define HD 128

// ---------------- device scratch ----------------
__device__ float g_hs  [(size_t)RR * NN * HD];
__device__ float g_acc [(size_t)RR * NN * HD];   // unnormalized sum of ex*hs
__device__ float g_el  [(size_t)RR * NN * HH];
__device__ float g_er  [(size_t)RR * NN * HH];
__device__ float g_ssum[(size_t)RR * NN * HH];
__device__ float g_WcT [RR * HIDD * HD];   // [r][n][k], tf32-rounded
__device__ float g_bc  [RR * HD];
__device__ float g_W1T [HD * 128];         // [n][k], tf32-rounded
__device__ float g_u   [RR * HIDD * HH];
__device__ float g_V   [RR * HIDD * HH];
__device__ float g_c   [RR * HH];
__device__ float g_wsum[RR];
__device__ float g_a   [RR];

// ---------------- helpers ----------------
__device__ __forceinline__ float to_tf32(float x) {
    uint32_t o;
    asm("cvt.rna.tf32.f32 %0, %1;" : "=r"(o) : "f"(x));
    return __uint_as_float(o);
}

__device__ __forceinline__ void redAdd4(float* addr, float4 v) {
    asm volatile("red.global.add.v4.f32 [%0], {%1,%2,%3,%4};"
                 :: "l"(addr), "f"(v.x), "f"(v.y), "f"(v.z), "f"(v.w) : "memory");
}

#define LDSM4(r0, r1, r2, r3, addr) \
    asm volatile("ldmatrix.sync.aligned.m8n8.x4.shared.b16 {%0,%1,%2,%3}, [%4];" \
                 : "=r"(r0), "=r"(r1), "=r"(r2), "=r"(r3) : "r"(addr))

#define MMA_TF32(c, a, b) \
    asm volatile("mma.sync.aligned.m16n8k8.row.col.f32.tf32.tf32.f32 " \
                 "{%0,%1,%2,%3},{%4,%5,%6,%7},{%8,%9},{%0,%1,%2,%3};" \
                 : "+f"((c)[0]), "+f"((c)[1]), "+f"((c)[2]), "+f"((c)[3]) \
                 : "r"((a)[0]), "r"((a)[1]), "r"((a)[2]), "r"((a)[3]), \
                   "r"((b)[0]), "r"((b)[1]))

// ---------------- init ----------------
__global__ void k_init() {
    int idx = blockIdx.x * blockDim.x + threadIdx.x;
    int stride = gridDim.x * blockDim.x;
    const int ACC4 = RR * NN * HD / 4;
    const int NH4  = RR * NN * HH / 4;
    float4 z4 = make_float4(0.f, 0.f, 0.f, 0.f);
    float4* acc4 = (float4*)g_acc;
    float4* s4   = (float4*)g_ssum;
    for (int i = idx; i < ACC4; i += stride) acc4[i] = z4;
    for (int i = idx; i < NH4; i += stride) s4[i] = z4;
    if (idx < RR) g_wsum[idx] = 0.f;
}

// ---------------- weight composition (writes W^T, tf32-rounded) ----------------
__global__ void k_combine(const float* __restrict__ Wt_src,
                          const float* __restrict__ bt_src,
                          const float* __restrict__ Wg) {
    int b = blockIdx.x;
    int r = b / (HIDD + 1);
    int i = b % (HIDD + 1);
    int tid = threadIdx.x;  // 128 = output col n
    __shared__ float srow[HIDD];
    const float* Wgr = Wg + (size_t)r * HIDD * HD;
    srow[tid] = (i < HIDD) ? Wt_src[((size_t)r * HIDD + i) * HIDD + tid]
                           : bt_src[r * HIDD + tid];
    __syncthreads();
    float acc = 0.f;
    #pragma unroll 8
    for (int k = 0; k < HIDD; k++) acc += srow[k] * Wgr[k * HD + tid];
    if (i < HIDD) g_WcT[((size_t)r * HIDD + tid) * HIDD + i] = to_tf32(acc);
    else          g_bc[r * HD + tid] = acc;
}

__global__ void k_w1t(const float* __restrict__ W1) {
    int idx = blockIdx.x * blockDim.x + threadIdx.x;
    if (idx >= HD * 128) return;
    int n = idx / 128, k = idx % 128;
    g_W1T[n * 128 + k] = to_tf32(W1[k * 128 + n]);
}

__global__ void k_u(const float* __restrict__ Wg, const float* __restrict__ attn_r) {
    int idx = blockIdx.x * blockDim.x + threadIdx.x;
    if (idx >= RR * HIDD * HH) return;
    int r = idx / (HIDD * HH);
    int rem = idx % (HIDD * HH);
    int k = rem / HH, h = rem % HH;
    const float* wg = Wg + (size_t)r * HIDD * HD + k * HD + h * 32;
    const float* ar = attn_r + r * HD + h * 32;
    float s = 0.f;
    #pragma unroll
    for (int d = 0; d < 32; d++) s += wg[d] * ar[d];
    g_u[idx] = s;
}

__global__ void k_V(const float* __restrict__ Wt_dst, const float* __restrict__ bt_dst) {
    int idx = blockIdx.x * blockDim.x + threadIdx.x;
    if (idx >= RR * HIDD * HH) return;
    int r = idx / (HIDD * HH);
    int rem = idx % (HIDD * HH);
    int f = rem / HH, h = rem % HH;
    const float* u = g_u + r * HIDD * HH;
    float s = 0.f;
    for (int k = 0; k < HIDD; k++) s += Wt_dst[f * HIDD + k] * u[k * HH + h];
    g_V[idx] = s;
    if (f == 0) {
        float c = 0.f;
        for (int k = 0; k < HIDD; k++) c += bt_dst[k] * u[k * HH + h];
        g_c[r * HH + h] = c;
    }
}

// ---------------- TF32 MMA GEMM geometry ----------------
constexpr int AS_STR = 20;
constexpr int WS_STR = 132;
constexpr int AS_BUF = 128 * AS_STR;
constexpr int SMEM_FLOATS = 128 * WS_STR + 2 * AS_BUF;

// ---------------- hs GEMM: g_hs = A @ Wc + bc, el epilogue ----------------
__global__ __launch_bounds__(256) void k_gemm_hs_mma(const float* __restrict__ src_feats,
                                                     const float* __restrict__ attn_l) {
    extern __shared__ float sm[];
    float* Ws = sm;
    float* As = sm + 128 * WS_STR;
    int tid = threadIdx.x;
    int r = blockIdx.y;
    int row0 = blockIdx.x * 128;
    const float* A = src_feats + (size_t)r * NN * HIDD;

    const float4* Wt4 = (const float4*)(g_WcT + (size_t)r * HIDD * HD);
    #pragma unroll
    for (int i = 0; i < 16; i++) {
        int idx = tid + i * 256;
        int n = idx >> 5, kq = idx & 31;
        *(float4*)(Ws + n * WS_STR + kq * 4) = Wt4[idx];
    }

    int grow = row0 + (tid >> 1);
    int koffA = (tid & 1) * 8;
    float4 areg0, areg1;
    float4 z4 = make_float4(0.f, 0.f, 0.f, 0.f);

    uint32_t sbase = (uint32_t)__cvta_generic_to_shared(sm);
    uint32_t asbase = sbase + 128 * WS_STR * 4;

    int lane = tid & 31, warp = tid >> 5;
    int warp_m = warp >> 1, warp_n = warp & 1;
    int n0 = warp_n * 64;
    int g = lane >> 2, tg = lane & 3;
    int grp = lane >> 3, rin = lane & 7;
    int arow = (grp & 1) * 8 + rin;
    int akoff = (grp >> 1) * 4;
    int brow = (grp >> 1) * 8 + rin;
    int bkoff = (grp & 1) * 4;

    uint32_t aAddr[2], bAddr[4];
    #pragma unroll
    for (int mt = 0; mt < 2; mt++)
        aAddr[mt] = asbase + ((warp_m * 32 + mt * 16 + arow) * AS_STR + akoff) * 4;
    #pragma unroll
    for (int pi = 0; pi < 4; pi++)
        bAddr[pi] = sbase + ((n0 + pi * 16 + brow) * WS_STR + bkoff) * 4;

    float c[2][8][4];
    #pragma unroll
    for (int mt = 0; mt < 2; mt++)
        #pragma unroll
        for (int nt = 0; nt < 8; nt++)
            #pragma unroll
            for (int q = 0; q < 4; q++) c[mt][nt][q] = 0.f;

    if (grow < NN) {
        const float4* p = (const float4*)(A + (size_t)grow * HIDD + koffA);
        areg0 = p[0]; areg1 = p[1];
    } else { areg0 = z4; areg1 = z4; }

    for (int kb = 0; kb < 8; kb++) {
        {
            float* dst = As + (kb & 1) * AS_BUF + (tid >> 1) * AS_STR + koffA;
            dst[0] = to_tf32(areg0.x); dst[1] = to_tf32(areg0.y);
            dst[2] = to_tf32(areg0.z); dst[3] = to_tf32(areg0.w);
            dst[4] = to_tf32(areg1.x); dst[5] = to_tf32(areg1.y);
            dst[6] = to_tf32(areg1.z); dst[7] = to_tf32(areg1.w);
        }
        if (kb < 7) {
            if (grow < NN) {
                const float4* p = (const float4*)(A + (size_t)grow * HIDD + (kb + 1) * 16 + koffA);
                areg0 = p[0]; areg1 = p[1];
            } else { areg0 = z4; areg1 = z4; }
        }
        __syncthreads();
        uint32_t abufoff = (kb & 1) * AS_BUF * 4;
        #pragma unroll
        for (int k8 = 0; k8 < 2; k8++) {
            uint32_t a[2][4], b[8][2];
            #pragma unroll
            for (int mt = 0; mt < 2; mt++)
                LDSM4(a[mt][0], a[mt][1], a[mt][2], a[mt][3],
                      aAddr[mt] + abufoff + k8 * 32);
            #pragma unroll
            for (int pi = 0; pi < 4; pi++)
                LDSM4(b[2 * pi][0], b[2 * pi][1], b[2 * pi + 1][0], b[2 * pi + 1][1],
                      bAddr[pi] + (kb * 16 + k8 * 8) * 4);
            #pragma unroll
            for (int mt = 0; mt < 2; mt++)
                #pragma unroll
                for (int nt = 0; nt < 8; nt++)
                    MMA_TF32(c[mt][nt], a[mt], b[nt]);
        }
    }

    float2 bc2[8], al2[8];
    #pragma unroll
    for (int nt = 0; nt < 8; nt++) {
        bc2[nt] = *(const float2*)(g_bc + r * HD + n0 + nt * 8 + 2 * tg);
        al2[nt] = *(const float2*)(attn_l + r * HD + n0 + nt * 8 + 2 * tg);
    }
    float elp[2][2][2];
    #pragma unroll
    for (int mt = 0; mt < 2; mt++)
        #pragma unroll
        for (int rh = 0; rh < 2; rh++) { elp[mt][rh][0] = 0.f; elp[mt][rh][1] = 0.f; }

    #pragma unroll
    for (int mt = 0; mt < 2; mt++) {
        int rowa = row0 + warp_m * 32 + mt * 16 + g;
        #pragma unroll
        for (int nt = 0; nt < 8; nt++) {
            float c0 = c[mt][nt][0] + bc2[nt].x, c1 = c[mt][nt][1] + bc2[nt].y;
            float c2 = c[mt][nt][2] + bc2[nt].x, c3 = c[mt][nt][3] + bc2[nt].y;
            int h = nt >> 2;
            elp[mt][0][h] += c0 * al2[nt].x + c1 * al2[nt].y;
            elp[mt][1][h] += c2 * al2[nt].x + c3 * al2[nt].y;
            if (rowa < NN)
                *(float2*)(g_hs + ((size_t)r * NN + rowa) * HD + n0 + nt * 8 + 2 * tg) = make_float2(c0, c1);
            if (rowa + 8 < NN)
                *(float2*)(g_hs + ((size_t)r * NN + rowa + 8) * HD + n0 + nt * 8 + 2 * tg) = make_float2(c2, c3);
        }
    }
    #pragma unroll
    for (int off = 1; off < 4; off <<= 1)
        #pragma unroll
        for (int mt = 0; mt < 2; mt++)
            #pragma unroll
            for (int rh = 0; rh < 2; rh++) {
                elp[mt][rh][0] += __shfl_xor_sync(0xffffffffu, elp[mt][rh][0], off);
                elp[mt][rh][1] += __shfl_xor_sync(0xffffffffu, elp[mt][rh][1], off);
            }
    if (tg == 0) {
        #pragma unroll
        for (int mt = 0; mt < 2; mt++)
            #pragma unroll
            for (int rh = 0; rh < 2; rh++) {
                int row = row0 + warp_m * 32 + mt * 16 + g + rh * 8;
                if (row < NN) {
                    g_el[((size_t)r * NN + row) * HH + warp_n * 2 + 0] = elp[mt][rh][0];
                    g_el[((size_t)r * NN + row) * HH + warp_n * 2 + 1] = elp[mt][rh][1];
                }
            }
    }
}

// ---------------- er: dst_feat @ V ----------------
__global__ void k_er(const float* __restrict__ dst_feat) {
    __shared__ float sV[RR * HIDD * HH];
    __shared__ float sc[RR * HH];
    int tid = threadIdx.x;
    for (int i = tid; i < RR * HIDD * HH; i += blockDim.x) sV[i] = g_V[i];
    if (tid < RR * HH) sc[tid] = g_c[tid];
    __syncthreads();
    int node = blockIdx.x * 8 + (tid >> 5);
    int lane = tid & 31;
    if (node >= NN) return;
    float4 f = ((const float4*)dst_feat)[(size_t)node * 32 + lane];
    #pragma unroll
    for (int r = 0; r < RR; r++) {
        const float* base = sV + r * HIDD * HH;
        float4 v0 = *(const float4*)(base + (lane * 4 + 0) * 4);
        float4 v1 = *(const float4*)(base + (lane * 4 + 1) * 4);
        float4 v2 = *(const float4*)(base + (lane * 4 + 2) * 4);
        float4 v3 = *(const float4*)(base + (lane * 4 + 3) * 4);
        float p0 = f.x * v0.x + f.y * v1.x + f.z * v2.x + f.w * v3.x;
        float p1 = f.x * v0.y + f.y * v1.y + f.z * v2.y + f.w * v3.y;
        float p2 = f.x * v0.z + f.y * v1.z + f.z * v2.z + f.w * v3.z;
        float p3 = f.x * v0.w + f.y * v1.w + f.z * v2.w + f.w * v3.w;
        #pragma unroll
        for (int off = 16; off; off >>= 1) {
            p0 += __shfl_xor_sync(0xffffffffu, p0, off);
            p1 += __shfl_xor_sync(0xffffffffu, p1, off);
            p2 += __shfl_xor_sync(0xffffffffu, p2, off);
            p3 += __shfl_xor_sync(0xffffffffu, p3, off);
        }
        if (lane == 0) {
            float* erp = g_er + ((size_t)r * NN + node) * HH;
            erp[0] = p0 + sc[r * HH + 0];
            erp[1] = p1 + sc[r * HH + 1];
            erp[2] = p2 + sc[r * HH + 2];
            erp[3] = p3 + sc[r * HH + 3];
        }
    }
}

// ---------------- fused edge pass: ex + unnormalized scatter + ssum ----------------
// warp per edge; softmax shift dropped (logits are O(1)), normalization deferred.
__global__ __launch_bounds__(256) void k_edge_fused(const int* __restrict__ src_idx,
                                                    const int* __restrict__ dst_idx) {
    int gt = blockIdx.x * blockDim.x + threadIdx.x;
    int w = gt >> 5, lane = gt & 31;
    if (w >= RR * EE) return;
    int r = w / EE;
    int s = src_idx[w], d = dst_idx[w];
    int h = lane >> 3;
    float e = g_el[((size_t)r * NN + s) * HH + h] + g_er[((size_t)r * NN + d) * HH + h];
    e = e > 0.f ? e : 0.2f * e;
    float ex = expf(e);
    float4 hv = *(const float4*)(g_hs + ((size_t)r * NN + s) * HD + lane * 4);
    redAdd4(g_acc + ((size_t)r * NN + d) * HD + lane * 4,
            make_float4(ex * hv.x, ex * hv.y, ex * hv.z, ex * hv.w));
    float v0  = __shfl_sync(0xffffffffu, ex, 0);
    float v8  = __shfl_sync(0xffffffffu, ex, 8);
    float v16 = __shfl_sync(0xffffffffu, ex, 16);
    float v24 = __shfl_sync(0xffffffffu, ex, 24);
    if (lane == 0)
        redAdd4(g_ssum + ((size_t)r * NN + d) * HH, make_float4(v0, v8, v16, v24));
}

// ---------------- semantic GEMM: normalize+bias+elu fused on load ----------------
__global__ __launch_bounds__(256) void k_semantic_mma(const float* __restrict__ bias_g,
                                                      const float* __restrict__ b1,
                                                      const float* __restrict__ W2) {
    extern __shared__ float sm[];
    float* Ws = sm;
    float* As = sm + 128 * WS_STR;
    __shared__ float sacc;
    int tid = threadIdx.x;
    if (tid == 0) sacc = 0.f;
    int r = blockIdx.y;
    int row0 = blockIdx.x * 128;
    const float* A = g_acc + (size_t)r * NN * HD;

    const float4* Wt4 = (const float4*)g_W1T;
    #pragma unroll
    for (int i = 0; i < 16; i++) {
        int idx = tid + i * 256;
        int n = idx >> 5, kq = idx & 31;
        *(float4*)(Ws + n * WS_STR + kq * 4) = Wt4[idx];
    }

    int grow = row0 + (tid >> 1);
    int koffA = (tid & 1) * 8;
    float4 areg0, areg1;
    float4 z4 = make_float4(0.f, 0.f, 0.f, 0.f);

    // per-row inverse softmax sums (one per head)
    float sinv[HH] = {0.f, 0.f, 0.f, 0.f};
    if (grow < NN) {
        float4 s4 = *(const float4*)(g_ssum + ((size_t)r * NN + grow) * HH);
        sinv[0] = 1.f / (s4.x + 1e-9f);
        sinv[1] = 1.f / (s4.y + 1e-9f);
        sinv[2] = 1.f / (s4.z + 1e-9f);
        sinv[3] = 1.f / (s4.w + 1e-9f);
    }

    uint32_t sbase = (uint32_t)__cvta_generic_to_shared(sm);
    uint32_t asbase = sbase + 128 * WS_STR * 4;

    int lane = tid & 31, warp = tid >> 5;
    int warp_m = warp >> 1, warp_n = warp & 1;
    int n0 = warp_n * 64;
    int g = lane >> 2, tg = lane & 3;
    int grp = lane >> 3, rin = lane & 7;
    int arow = (grp & 1) * 8 + rin;
    int akoff = (grp >> 1) * 4;
    int brow = (grp >> 1) * 8 + rin;
    int bkoff = (grp & 1) * 4;

    uint32_t aAddr[2], bAddr[4];
    #pragma unroll
    for (int mt = 0; mt < 2; mt++)
        aAddr[mt] = asbase + ((warp_m * 32 + mt * 16 + arow) * AS_STR + akoff) * 4;
    #pragma unroll
    for (int pi = 0; pi < 4; pi++)
        bAddr[pi] = sbase + ((n0 + pi * 16 + brow) * WS_STR + bkoff) * 4;

    float c[2][8][4];
    #pragma unroll
    for (int mt = 0; mt < 2; mt++)
        #pragma unroll
        for (int nt = 0; nt < 8; nt++)
            #pragma unroll
            for (int q = 0; q < 4; q++) c[mt][nt][q] = 0.f;

    auto loadT = [&](int kb) {
        if (grow < NN) {
            const float* p = A + (size_t)grow * HD + kb * 16 + koffA;
            float4 v0 = ((const float4*)p)[0], v1 = ((const float4*)p)[1];
            float4 bg0 = *(const float4*)(bias_g + r * HD + kb * 16 + koffA);
            float4 bg1 = *(const float4*)(bias_g + r * HD + kb * 16 + koffA + 4);
            float si = sinv[(kb * 16 + koffA) >> 5];  // 8 cols stay in one head
            v0.x = v0.x * si + bg0.x; v0.y = v0.y * si + bg0.y;
            v0.z = v0.z * si + bg0.z; v0.w = v0.w * si + bg0.w;
            v1.x = v1.x * si + bg1.x; v1.y = v1.y * si + bg1.y;
            v1.z = v1.z * si + bg1.z; v1.w = v1.w * si + bg1.w;
            v0.x = v0.x > 0.f ? v0.x : expm1f(v0.x);
            v0.y = v0.y > 0.f ? v0.y : expm1f(v0.y);
            v0.z = v0.z > 0.f ? v0.z : expm1f(v0.z);
            v0.w = v0.w > 0.f ? v0.w : expm1f(v0.w);
            v1.x = v1.x > 0.f ? v1.x : expm1f(v1.x);
            v1.y = v1.y > 0.f ? v1.y : expm1f(v1.y);
            v1.z = v1.z > 0.f ? v1.z : expm1f(v1.z);
            v1.w = v1.w > 0.f ? v1.w : expm1f(v1.w);
            areg0 = v0; areg1 = v1;
        } else { areg0 = z4; areg1 = z4; }
    };

    loadT(0);
    for (int kb = 0; kb < 8; kb++) {
        {
            float* dst = As + (kb & 1) * AS_BUF + (tid >> 1) * AS_STR + koffA;
            dst[0] = to_tf32(areg0.x); dst[1] = to_tf32(areg0.y);
            dst[2] = to_tf32(areg0.z); dst[3] = to_tf32(areg0.w);
            dst[4] = to_tf32(areg1.x); dst[5] = to_tf32(areg1.y);
            dst[6] = to_tf32(areg1.z); dst[7] = to_tf32(areg1.w);
        }
        if (kb < 7) loadT(kb + 1);
        __syncthreads();
        uint32_t abufoff = (kb & 1) * AS_BUF * 4;
        #pragma unroll
        for (int k8 = 0; k8 < 2; k8++) {
            uint32_t a[2][4], b[8][2];
            #pragma unroll
            for (int mt = 0; mt < 2; mt++)
                LDSM4(a[mt][0], a[mt][1], a[mt][2], a[mt][3],
                      aAddr[mt] + abufoff + k8 * 32);
            #pragma unroll
            for (int pi = 0; pi < 4; pi++)
                LDSM4(b[2 * pi][0], b[2 * pi][1], b[2 * pi + 1][0], b[2 * pi + 1][1],
                      bAddr[pi] + (kb * 16 + k8 * 8) * 4);
            #pragma unroll
            for (int mt = 0; mt < 2; mt++)
                #pragma unroll
                for (int nt = 0; nt < 8; nt++)
                    MMA_TF32(c[mt][nt], a[mt], b[nt]);
        }
    }

    float2 b12[8], w22[8];
    #pragma unroll
    for (int nt = 0; nt < 8; nt++) {
        b12[nt] = *(const float2*)(b1 + n0 + nt * 8 + 2 * tg);
        w22[nt] = *(const float2*)(W2 + n0 + nt * 8 + 2 * tg);
    }
    float ps[2][2] = {{0.f, 0.f}, {0.f, 0.f}};
    #pragma unroll
    for (int mt = 0; mt < 2; mt++)
        #pragma unroll
        for (int nt = 0; nt < 8; nt++) {
            ps[mt][0] += tanhf(c[mt][nt][0] + b12[nt].x) * w22[nt].x
                       + tanhf(c[mt][nt][1] + b12[nt].y) * w22[nt].y;
            ps[mt][1] += tanhf(c[mt][nt][2] + b12[nt].x) * w22[nt].x
                       + tanhf(c[mt][nt][3] + b12[nt].y) * w22[nt].y;
        }
    #pragma unroll
    for (int off = 1; off < 4; off <<= 1)
        #pragma unroll
        for (int mt = 0; mt < 2; mt++) {
            ps[mt][0] += __shfl_xor_sync(0xffffffffu, ps[mt][0], off);
            ps[mt][1] += __shfl_xor_sync(0xffffffffu, ps[mt][1], off);
        }
    if (tg == 0) {
        float loc = 0.f;
        #pragma unroll
        for (int mt = 0; mt < 2; mt++)
            #pragma unroll
            for (int rh = 0; rh < 2; rh++) {
                int row = row0 + warp_m * 32 + mt * 16 + g + rh * 8;
                if (row < NN) loc += ps[mt][rh];
            }
        atomicAdd(&sacc, loc);
    }
    __syncthreads();
    if (tid == 0) atomicAdd(&g_wsum[r], sacc);
}

// ---------------- semantic softmax ----------------
__global__ void k_softmax(float* __restrict__ out) {
    int t = threadIdx.x;
    if (t < RR) {
        float w0 = g_wsum[0] / (float)NN;
        float w1 = g_wsum[1] / (float)NN;
        float w2 = g_wsum[2] / (float)NN;
        float mx = fmaxf(w0, fmaxf(w1, w2));
        float e0 = expf(w0 - mx), e1 = expf(w1 - mx), e2 = expf(w2 - mx);
        float s = e0 + e1 + e2;
        float a = (t == 0 ? e0 : (t == 1 ? e1 : e2)) / s;
        g_a[t] = a;
        out[(size_t)NN * HD + t] = a;
    }
}

// ---------------- final combine (recompute z_r from acc/ssum/bias) ----------------
__global__ void k_final(const float* __restrict__ bias_g, float* __restrict__ out) {
    int idx = blockIdx.x * blockDim.x + threadIdx.x;
    const int TOT4 = NN * HD / 4;
    if (idx >= TOT4) return;
    float a[RR] = {__ldg(&g_a[0]), __ldg(&g_a[1]), __ldg(&g_a[2])};
    int node = idx >> 5;           // idx*4 / 128
    int col0 = (idx & 31) * 4;     // idx*4 % 128
    int head = col0 >> 5;
    float4 o = make_float4(0.f, 0.f, 0.f, 0.f);
    #pragma unroll
    for (int r = 0; r < RR; r++) {
        float si = 1.f / (g_ssum[((size_t)r * NN + node) * HH + head] + 1e-9f);
        float4 v = *(const float4*)(g_acc + ((size_t)r * NN + node) * HD + col0);
        float4 bg = *(const float4*)(bias_g + r * HD + col0);
        v.x = v.x * si + bg.x; v.y = v.y * si + bg.y;
        v.z = v.z * si + bg.z; v.w = v.w * si + bg.w;
        v.x = v.x > 0.f ? v.x : expm1f(v.x);
        v.y = v.y > 0.f ? v.y : expm1f(v.y);
        v.z = v.z > 0.f ? v.z : expm1f(v.z);
        v.w = v.w > 0.f ? v.w : expm1f(v.w);
        o.x += a[r] * v.x; o.y += a[r] * v.y;
        o.z += a[r] * v.z; o.w += a[r] * v.w;
    }
    ((float4*)out)[idx] = o;
}

// ---------------- launch ----------------
extern "C" void kernel_launch(void* const* d_in, const int* in_sizes, int n_in,
                              void* d_out, int out_size) {
    const float* dst_feat  = (const float*)d_in[0];
    const float* src_feats = (const float*)d_in[1];
    const int*   src_idx   = (const int*)d_in[2];
    const int*   dst_idx   = (const int*)d_in[3];
    const float* Wt_dst    = (const float*)d_in[4];
    const float* bt_dst    = (const float*)d_in[5];
    const float* Wt_src    = (const float*)d_in[6];
    const float* bt_src    = (const float*)d_in[7];
    const float* Wg        = (const float*)d_in[8];
    const float* attn_l    = (const float*)d_in[9];
    const float* attn_r    = (const float*)d_in[10];
    const float* bias_g    = (const float*)d_in[11];
    const float* W1        = (const float*)d_in[12];
    const float* b1        = (const float*)d_in[13];
    const float* W2        = (const float*)d_in[14];
    float* out = (float*)d_out;

    size_t smem_mma = (size_t)SMEM_FLOATS * sizeof(float);
    cudaFuncSetAttribute(k_gemm_hs_mma, cudaFuncAttributeMaxDynamicSharedMemorySize, (int)smem_mma);
    cudaFuncSetAttribute(k_semantic_mma, cudaFuncAttributeMaxDynamicSharedMemorySize, (int)smem_mma);

    k_init<<<2048, 256>>>();
    k_combine<<<RR * (HIDD + 1), HIDD>>>(Wt_src, bt_src, Wg);
    k_w1t<<<(HD * 128 + 255) / 256, 256>>>(W1);
    k_u<<<(RR * HIDD * HH + 127) / 128, 128>>>(Wg, attn_r);
    k_V<<<(RR * HIDD * HH + 127) / 128, 128>>>(Wt_dst, bt_dst);

    dim3 ggrid((NN + 127) / 128, RR);
    k_gemm_hs_mma<<<ggrid, 256, smem_mma>>>(src_feats, attn_l);
    k_er<<<(NN + 7) / 8, 256>>>(dst_feat);

    int eth = RR * EE;
    k_edge_fused<<<(eth * 32 + 255) / 256, 256>>>(src_idx, dst_idx);

    k_semantic_mma<<<ggrid, 256, smem_mma>>>(bias_g, b1, W2);
    k_softmax<<<1, 32>>>(out);
    k_final<<<(NN * HD / 4 + 255) / 256, 256>>>(bias_g, out);
}

// round 4
// speedup vs baseline: 1.4059x; 1.4059x over previous
#include <cuda_runtime.h>
#include <math.h>
#include <stdint.h>

#define NN 100000
#define RR 3
#define EE 320000
#define HIDD 128
#define HH 4
#define HD 128

// ---------------- device scratch ----------------
__device__ float g_hs  [(size_t)RR * NN * HD];
__device__ float g_acc [(size_t)RR * NN * HD];   // unnormalized sum of ex*hs
__device__ float g_el  [(size_t)RR * NN * HH];
__device__ float g_er  [(size_t)RR * NN * HH];
__device__ float g_e   [(size_t)RR * EE * HH];   // ex per edge
__device__ float g_ssum[(size_t)RR * NN * HH];
__device__ float g_WcT [RR * HIDD * HD];   // [r][n][k], tf32-rounded
__device__ float g_bc  [RR * HD];
__device__ float g_W1T [HD * 128];         // [n][k], tf32-rounded
__device__ float g_u   [RR * HIDD * HH];
__device__ float g_V   [RR * HIDD * HH];
__device__ float g_c   [RR * HH];
__device__ float g_wsum[RR];
__device__ float g_a   [RR];

// ---------------- helpers ----------------
__device__ __forceinline__ float to_tf32(float x) {
    uint32_t o;
    asm("cvt.rna.tf32.f32 %0, %1;" : "=r"(o) : "f"(x));
    return __uint_as_float(o);
}

__device__ __forceinline__ void redAdd4(float* addr, float4 v) {
    asm volatile("red.global.add.v4.f32 [%0], {%1,%2,%3,%4};"
                 :: "l"(addr), "f"(v.x), "f"(v.y), "f"(v.z), "f"(v.w) : "memory");
}

#define LDSM4(r0, r1, r2, r3, addr) \
    asm volatile("ldmatrix.sync.aligned.m8n8.x4.shared.b16 {%0,%1,%2,%3}, [%4];" \
                 : "=r"(r0), "=r"(r1), "=r"(r2), "=r"(r3) : "r"(addr))

#define MMA_TF32(c, a, b) \
    asm volatile("mma.sync.aligned.m16n8k8.row.col.f32.tf32.tf32.f32 " \
                 "{%0,%1,%2,%3},{%4,%5,%6,%7},{%8,%9},{%0,%1,%2,%3};" \
                 : "+f"((c)[0]), "+f"((c)[1]), "+f"((c)[2]), "+f"((c)[3]) \
                 : "r"((a)[0]), "r"((a)[1]), "r"((a)[2]), "r"((a)[3]), \
                   "r"((b)[0]), "r"((b)[1]))

// ---------------- init ----------------
__global__ void k_init() {
    int idx = blockIdx.x * blockDim.x + threadIdx.x;
    int stride = gridDim.x * blockDim.x;
    const int ACC4 = RR * NN * HD / 4;
    const int NH4  = RR * NN * HH / 4;
    float4 z4 = make_float4(0.f, 0.f, 0.f, 0.f);
    float4* acc4 = (float4*)g_acc;
    float4* s4   = (float4*)g_ssum;
    for (int i = idx; i < ACC4; i += stride) acc4[i] = z4;
    for (int i = idx; i < NH4; i += stride) s4[i] = z4;
    if (idx < RR) g_wsum[idx] = 0.f;
}

// ---------------- weight composition (writes W^T, tf32-rounded) ----------------
__global__ void k_combine(const float* __restrict__ Wt_src,
                          const float* __restrict__ bt_src,
                          const float* __restrict__ Wg) {
    int b = blockIdx.x;
    int r = b / (HIDD + 1);
    int i = b % (HIDD + 1);
    int tid = threadIdx.x;  // 128 = output col n
    __shared__ float srow[HIDD];
    const float* Wgr = Wg + (size_t)r * HIDD * HD;
    srow[tid] = (i < HIDD) ? Wt_src[((size_t)r * HIDD + i) * HIDD + tid]
                           : bt_src[r * HIDD + tid];
    __syncthreads();
    float acc = 0.f;
    #pragma unroll 8
    for (int k = 0; k < HIDD; k++) acc += srow[k] * Wgr[k * HD + tid];
    if (i < HIDD) g_WcT[((size_t)r * HIDD + tid) * HIDD + i] = to_tf32(acc);
    else          g_bc[r * HD + tid] = acc;
}

__global__ void k_w1t(const float* __restrict__ W1) {
    int idx = blockIdx.x * blockDim.x + threadIdx.x;
    if (idx >= HD * 128) return;
    int n = idx / 128, k = idx % 128;
    g_W1T[n * 128 + k] = to_tf32(W1[k * 128 + n]);
}

__global__ void k_u(const float* __restrict__ Wg, const float* __restrict__ attn_r) {
    int idx = blockIdx.x * blockDim.x + threadIdx.x;
    if (idx >= RR * HIDD * HH) return;
    int r = idx / (HIDD * HH);
    int rem = idx % (HIDD * HH);
    int k = rem / HH, h = rem % HH;
    const float* wg = Wg + (size_t)r * HIDD * HD + k * HD + h * 32;
    const float* ar = attn_r + r * HD + h * 32;
    float s = 0.f;
    #pragma unroll
    for (int d = 0; d < 32; d++) s += wg[d] * ar[d];
    g_u[idx] = s;
}

__global__ void k_V(const float* __restrict__ Wt_dst, const float* __restrict__ bt_dst) {
    int idx = blockIdx.x * blockDim.x + threadIdx.x;
    if (idx >= RR * HIDD * HH) return;
    int r = idx / (HIDD * HH);
    int rem = idx % (HIDD * HH);
    int f = rem / HH, h = rem % HH;
    const float* u = g_u + r * HIDD * HH;
    float s = 0.f;
    for (int k = 0; k < HIDD; k++) s += Wt_dst[f * HIDD + k] * u[k * HH + h];
    g_V[idx] = s;
    if (f == 0) {
        float c = 0.f;
        for (int k = 0; k < HIDD; k++) c += bt_dst[k] * u[k * HH + h];
        g_c[r * HH + h] = c;
    }
}

// ---------------- TF32 MMA GEMM geometry ----------------
constexpr int AS_STR = 20;
constexpr int WS_STR = 132;
constexpr int AS_BUF = 128 * AS_STR;
constexpr int SMEM_FLOATS = 128 * WS_STR + 2 * AS_BUF;

// ---------------- hs GEMM: g_hs = A @ Wc + bc, el epilogue ----------------
__global__ __launch_bounds__(256) void k_gemm_hs_mma(const float* __restrict__ src_feats,
                                                     const float* __restrict__ attn_l) {
    extern __shared__ float sm[];
    float* Ws = sm;
    float* As = sm + 128 * WS_STR;
    int tid = threadIdx.x;
    int r = blockIdx.y;
    int row0 = blockIdx.x * 128;
    const float* A = src_feats + (size_t)r * NN * HIDD;

    const float4* Wt4 = (const float4*)(g_WcT + (size_t)r * HIDD * HD);
    #pragma unroll
    for (int i = 0; i < 16; i++) {
        int idx = tid + i * 256;
        int n = idx >> 5, kq = idx & 31;
        *(float4*)(Ws + n * WS_STR + kq * 4) = Wt4[idx];
    }

    int grow = row0 + (tid >> 1);
    int koffA = (tid & 1) * 8;
    float4 areg0, areg1;
    float4 z4 = make_float4(0.f, 0.f, 0.f, 0.f);

    uint32_t sbase = (uint32_t)__cvta_generic_to_shared(sm);
    uint32_t asbase = sbase + 128 * WS_STR * 4;

    int lane = tid & 31, warp = tid >> 5;
    int warp_m = warp >> 1, warp_n = warp & 1;
    int n0 = warp_n * 64;
    int g = lane >> 2, tg = lane & 3;
    int grp = lane >> 3, rin = lane & 7;
    int arow = (grp & 1) * 8 + rin;
    int akoff = (grp >> 1) * 4;
    int brow = (grp >> 1) * 8 + rin;
    int bkoff = (grp & 1) * 4;

    uint32_t aAddr[2], bAddr[4];
    #pragma unroll
    for (int mt = 0; mt < 2; mt++)
        aAddr[mt] = asbase + ((warp_m * 32 + mt * 16 + arow) * AS_STR + akoff) * 4;
    #pragma unroll
    for (int pi = 0; pi < 4; pi++)
        bAddr[pi] = sbase + ((n0 + pi * 16 + brow) * WS_STR + bkoff) * 4;

    float c[2][8][4];
    #pragma unroll
    for (int mt = 0; mt < 2; mt++)
        #pragma unroll
        for (int nt = 0; nt < 8; nt++)
            #pragma unroll
            for (int q = 0; q < 4; q++) c[mt][nt][q] = 0.f;

    if (grow < NN) {
        const float4* p = (const float4*)(A + (size_t)grow * HIDD + koffA);
        areg0 = p[0]; areg1 = p[1];
    } else { areg0 = z4; areg1 = z4; }

    for (int kb = 0; kb < 8; kb++) {
        {
            float* dst = As + (kb & 1) * AS_BUF + (tid >> 1) * AS_STR + koffA;
            dst[0] = to_tf32(areg0.x); dst[1] = to_tf32(areg0.y);
            dst[2] = to_tf32(areg0.z); dst[3] = to_tf32(areg0.w);
            dst[4] = to_tf32(areg1.x); dst[5] = to_tf32(areg1.y);
            dst[6] = to_tf32(areg1.z); dst[7] = to_tf32(areg1.w);
        }
        if (kb < 7) {
            if (grow < NN) {
                const float4* p = (const float4*)(A + (size_t)grow * HIDD + (kb + 1) * 16 + koffA);
                areg0 = p[0]; areg1 = p[1];
            } else { areg0 = z4; areg1 = z4; }
        }
        __syncthreads();
        uint32_t abufoff = (kb & 1) * AS_BUF * 4;
        #pragma unroll
        for (int k8 = 0; k8 < 2; k8++) {
            uint32_t a[2][4], b[8][2];
            #pragma unroll
            for (int mt = 0; mt < 2; mt++)
                LDSM4(a[mt][0], a[mt][1], a[mt][2], a[mt][3],
                      aAddr[mt] + abufoff + k8 * 32);
            #pragma unroll
            for (int pi = 0; pi < 4; pi++)
                LDSM4(b[2 * pi][0], b[2 * pi][1], b[2 * pi + 1][0], b[2 * pi + 1][1],
                      bAddr[pi] + (kb * 16 + k8 * 8) * 4);
            #pragma unroll
            for (int mt = 0; mt < 2; mt++)
                #pragma unroll
                for (int nt = 0; nt < 8; nt++)
                    MMA_TF32(c[mt][nt], a[mt], b[nt]);
        }
    }

    float2 bc2[8], al2[8];
    #pragma unroll
    for (int nt = 0; nt < 8; nt++) {
        bc2[nt] = *(const float2*)(g_bc + r * HD + n0 + nt * 8 + 2 * tg);
        al2[nt] = *(const float2*)(attn_l + r * HD + n0 + nt * 8 + 2 * tg);
    }
    float elp[2][2][2];
    #pragma unroll
    for (int mt = 0; mt < 2; mt++)
        #pragma unroll
        for (int rh = 0; rh < 2; rh++) { elp[mt][rh][0] = 0.f; elp[mt][rh][1] = 0.f; }

    #pragma unroll
    for (int mt = 0; mt < 2; mt++) {
        int rowa = row0 + warp_m * 32 + mt * 16 + g;
        #pragma unroll
        for (int nt = 0; nt < 8; nt++) {
            float c0 = c[mt][nt][0] + bc2[nt].x, c1 = c[mt][nt][1] + bc2[nt].y;
            float c2 = c[mt][nt][2] + bc2[nt].x, c3 = c[mt][nt][3] + bc2[nt].y;
            int h = nt >> 2;
            elp[mt][0][h] += c0 * al2[nt].x + c1 * al2[nt].y;
            elp[mt][1][h] += c2 * al2[nt].x + c3 * al2[nt].y;
            if (rowa < NN)
                *(float2*)(g_hs + ((size_t)r * NN + rowa) * HD + n0 + nt * 8 + 2 * tg) = make_float2(c0, c1);
            if (rowa + 8 < NN)
                *(float2*)(g_hs + ((size_t)r * NN + rowa + 8) * HD + n0 + nt * 8 + 2 * tg) = make_float2(c2, c3);
        }
    }
    #pragma unroll
    for (int off = 1; off < 4; off <<= 1)
        #pragma unroll
        for (int mt = 0; mt < 2; mt++)
            #pragma unroll
            for (int rh = 0; rh < 2; rh++) {
                elp[mt][rh][0] += __shfl_xor_sync(0xffffffffu, elp[mt][rh][0], off);
                elp[mt][rh][1] += __shfl_xor_sync(0xffffffffu, elp[mt][rh][1], off);
            }
    if (tg == 0) {
        #pragma unroll
        for (int mt = 0; mt < 2; mt++)
            #pragma unroll
            for (int rh = 0; rh < 2; rh++) {
                int row = row0 + warp_m * 32 + mt * 16 + g + rh * 8;
                if (row < NN) {
                    g_el[((size_t)r * NN + row) * HH + warp_n * 2 + 0] = elp[mt][rh][0];
                    g_el[((size_t)r * NN + row) * HH + warp_n * 2 + 1] = elp[mt][rh][1];
                }
            }
    }
}

// ---------------- er: dst_feat @ V ----------------
__global__ void k_er(const float* __restrict__ dst_feat) {
    __shared__ float sV[RR * HIDD * HH];
    __shared__ float sc[RR * HH];
    int tid = threadIdx.x;
    for (int i = tid; i < RR * HIDD * HH; i += blockDim.x) sV[i] = g_V[i];
    if (tid < RR * HH) sc[tid] = g_c[tid];
    __syncthreads();
    int node = blockIdx.x * 8 + (tid >> 5);
    int lane = tid & 31;
    if (node >= NN) return;
    float4 f = ((const float4*)dst_feat)[(size_t)node * 32 + lane];
    #pragma unroll
    for (int r = 0; r < RR; r++) {
        const float* base = sV + r * HIDD * HH;
        float4 v0 = *(const float4*)(base + (lane * 4 + 0) * 4);
        float4 v1 = *(const float4*)(base + (lane * 4 + 1) * 4);
        float4 v2 = *(const float4*)(base + (lane * 4 + 2) * 4);
        float4 v3 = *(const float4*)(base + (lane * 4 + 3) * 4);
        float p0 = f.x * v0.x + f.y * v1.x + f.z * v2.x + f.w * v3.x;
        float p1 = f.x * v0.y + f.y * v1.y + f.z * v2.y + f.w * v3.y;
        float p2 = f.x * v0.z + f.y * v1.z + f.z * v2.z + f.w * v3.z;
        float p3 = f.x * v0.w + f.y * v1.w + f.z * v2.w + f.w * v3.w;
        #pragma unroll
        for (int off = 16; off; off >>= 1) {
            p0 += __shfl_xor_sync(0xffffffffu, p0, off);
            p1 += __shfl_xor_sync(0xffffffffu, p1, off);
            p2 += __shfl_xor_sync(0xffffffffu, p2, off);
            p3 += __shfl_xor_sync(0xffffffffu, p3, off);
        }
        if (lane == 0) {
            float* erp = g_er + ((size_t)r * NN + node) * HH;
            erp[0] = p0 + sc[r * HH + 0];
            erp[1] = p1 + sc[r * HH + 1];
            erp[2] = p2 + sc[r * HH + 2];
            erp[3] = p3 + sc[r * HH + 3];
        }
    }
}

// ---------------- edge pass A: ex = exp(leaky(el+er)), store + ssum ----------------
// (no max-shift: softmax is shift-invariant; logits are O(1) here)
__global__ void k_edge_exp(const int* __restrict__ src_idx, const int* __restrict__ dst_idx) {
    int idx = blockIdx.x * blockDim.x + threadIdx.x;
    if (idx >= RR * EE) return;
    int r = idx / EE;
    int s = src_idx[idx], d = dst_idx[idx];
    float4 el4 = *(const float4*)(g_el + ((size_t)r * NN + s) * HH);
    float4 er4 = *(const float4*)(g_er + ((size_t)r * NN + d) * HH);
    float4 v = make_float4(el4.x + er4.x, el4.y + er4.y, el4.z + er4.z, el4.w + er4.w);
    v.x = v.x > 0.f ? v.x : 0.2f * v.x;
    v.y = v.y > 0.f ? v.y : 0.2f * v.y;
    v.z = v.z > 0.f ? v.z : 0.2f * v.z;
    v.w = v.w > 0.f ? v.w : 0.2f * v.w;
    float4 ex = make_float4(expf(v.x), expf(v.y), expf(v.z), expf(v.w));
    *(float4*)(g_e + (size_t)idx * HH) = ex;
    redAdd4(g_ssum + ((size_t)r * NN + d) * HH, ex);
}

// ---------------- edge pass B: unnormalized weighted scatter (warp per edge) ----------------
__global__ void k_scatter(const int* __restrict__ src_idx, const int* __restrict__ dst_idx) {
    int gt = blockIdx.x * blockDim.x + threadIdx.x;
    int w = gt >> 5, lane = gt & 31;
    if (w >= RR * EE) return;
    int r = w / EE;
    int s = src_idx[w], d = dst_idx[w];
    int h = lane >> 3;
    float ex = g_e[(size_t)w * HH + h];
    float4 hv = *(const float4*)(g_hs + ((size_t)r * NN + s) * HD + lane * 4);
    redAdd4(g_acc + ((size_t)r * NN + d) * HD + lane * 4,
            make_float4(ex * hv.x, ex * hv.y, ex * hv.z, ex * hv.w));
}

// ---------------- semantic GEMM: normalize+bias+elu fused on load ----------------
__global__ __launch_bounds__(256) void k_semantic_mma(const float* __restrict__ bias_g,
                                                      const float* __restrict__ b1,
                                                      const float* __restrict__ W2) {
    extern __shared__ float sm[];
    float* Ws = sm;
    float* As = sm + 128 * WS_STR;
    __shared__ float sacc;
    int tid = threadIdx.x;
    if (tid == 0) sacc = 0.f;
    int r = blockIdx.y;
    int row0 = blockIdx.x * 128;
    const float* A = g_acc + (size_t)r * NN * HD;

    const float4* Wt4 = (const float4*)g_W1T;
    #pragma unroll
    for (int i = 0; i < 16; i++) {
        int idx = tid + i * 256;
        int n = idx >> 5, kq = idx & 31;
        *(float4*)(Ws + n * WS_STR + kq * 4) = Wt4[idx];
    }

    int grow = row0 + (tid >> 1);
    int koffA = (tid & 1) * 8;
    float4 areg0, areg1;
    float4 z4 = make_float4(0.f, 0.f, 0.f, 0.f);

    float sinv[HH] = {0.f, 0.f, 0.f, 0.f};
    if (grow < NN) {
        float4 s4 = *(const float4*)(g_ssum + ((size_t)r * NN + grow) * HH);
        sinv[0] = 1.f / (s4.x + 1e-9f);
        sinv[1] = 1.f / (s4.y + 1e-9f);
        sinv[2] = 1.f / (s4.z + 1e-9f);
        sinv[3] = 1.f / (s4.w + 1e-9f);
    }

    uint32_t sbase = (uint32_t)__cvta_generic_to_shared(sm);
    uint32_t asbase = sbase + 128 * WS_STR * 4;

    int lane = tid & 31, warp = tid >> 5;
    int warp_m = warp >> 1, warp_n = warp & 1;
    int n0 = warp_n * 64;
    int g = lane >> 2, tg = lane & 3;
    int grp = lane >> 3, rin = lane & 7;
    int arow = (grp & 1) * 8 + rin;
    int akoff = (grp >> 1) * 4;
    int brow = (grp >> 1) * 8 + rin;
    int bkoff = (grp & 1) * 4;

    uint32_t aAddr[2], bAddr[4];
    #pragma unroll
    for (int mt = 0; mt < 2; mt++)
        aAddr[mt] = asbase + ((warp_m * 32 + mt * 16 + arow) * AS_STR + akoff) * 4;
    #pragma unroll
    for (int pi = 0; pi < 4; pi++)
        bAddr[pi] = sbase + ((n0 + pi * 16 + brow) * WS_STR + bkoff) * 4;

    float c[2][8][4];
    #pragma unroll
    for (int mt = 0; mt < 2; mt++)
        #pragma unroll
        for (int nt = 0; nt < 8; nt++)
            #pragma unroll
            for (int q = 0; q < 4; q++) c[mt][nt][q] = 0.f;

    auto loadT = [&](int kb) {
        if (grow < NN) {
            const float* p = A + (size_t)grow * HD + kb * 16 + koffA;
            float4 v0 = ((const float4*)p)[0], v1 = ((const float4*)p)[1];
            float4 bg0 = *(const float4*)(bias_g + r * HD + kb * 16 + koffA);
            float4 bg1 = *(const float4*)(bias_g + r * HD + kb * 16 + koffA + 4);
            float si = sinv[(kb * 16 + koffA) >> 5];
            v0.x = v0.x * si + bg0.x; v0.y = v0.y * si + bg0.y;
            v0.z = v0.z * si + bg0.z; v0.w = v0.w * si + bg0.w;
            v1.x = v1.x * si + bg1.x; v1.y = v1.y * si + bg1.y;
            v1.z = v1.z * si + bg1.z; v1.w = v1.w * si + bg1.w;
            v0.x = v0.x > 0.f ? v0.x : expm1f(v0.x);
            v0.y = v0.y > 0.f ? v0.y : expm1f(v0.y);
            v0.z = v0.z > 0.f ? v0.z : expm1f(v0.z);
            v0.w = v0.w > 0.f ? v0.w : expm1f(v0.w);
            v1.x = v1.x > 0.f ? v1.x : expm1f(v1.x);
            v1.y = v1.y > 0.f ? v1.y : expm1f(v1.y);
            v1.z = v1.z > 0.f ? v1.z : expm1f(v1.z);
            v1.w = v1.w > 0.f ? v1.w : expm1f(v1.w);
            areg0 = v0; areg1 = v1;
        } else { areg0 = z4; areg1 = z4; }
    };

    loadT(0);
    for (int kb = 0; kb < 8; kb++) {
        {
            float* dst = As + (kb & 1) * AS_BUF + (tid >> 1) * AS_STR + koffA;
            dst[0] = to_tf32(areg0.x); dst[1] = to_tf32(areg0.y);
            dst[2] = to_tf32(areg0.z); dst[3] = to_tf32(areg0.w);
            dst[4] = to_tf32(areg1.x); dst[5] = to_tf32(areg1.y);
            dst[6] = to_tf32(areg1.z); dst[7] = to_tf32(areg1.w);
        }
        if (kb < 7) loadT(kb + 1);
        __syncthreads();
        uint32_t abufoff = (kb & 1) * AS_BUF * 4;
        #pragma unroll
        for (int k8 = 0; k8 < 2; k8++) {
            uint32_t a[2][4], b[8][2];
            #pragma unroll
            for (int mt = 0; mt < 2; mt++)
                LDSM4(a[mt][0], a[mt][1], a[mt][2], a[mt][3],
                      aAddr[mt] + abufoff + k8 * 32);
            #pragma unroll
            for (int pi = 0; pi < 4; pi++)
                LDSM4(b[2 * pi][0], b[2 * pi][1], b[2 * pi + 1][0], b[2 * pi + 1][1],
                      bAddr[pi] + (kb * 16 + k8 * 8) * 4);
            #pragma unroll
            for (int mt = 0; mt < 2; mt++)
                #pragma unroll
                for (int nt = 0; nt < 8; nt++)
                    MMA_TF32(c[mt][nt], a[mt], b[nt]);
        }
    }

    float2 b12[8], w22[8];
    #pragma unroll
    for (int nt = 0; nt < 8; nt++) {
        b12[nt] = *(const float2*)(b1 + n0 + nt * 8 + 2 * tg);
        w22[nt] = *(const float2*)(W2 + n0 + nt * 8 + 2 * tg);
    }
    float ps[2][2] = {{0.f, 0.f}, {0.f, 0.f}};
    #pragma unroll
    for (int mt = 0; mt < 2; mt++)
        #pragma unroll
        for (int nt = 0; nt < 8; nt++) {
            ps[mt][0] += tanhf(c[mt][nt][0] + b12[nt].x) * w22[nt].x
                       + tanhf(c[mt][nt][1] + b12[nt].y) * w22[nt].y;
            ps[mt][1] += tanhf(c[mt][nt][2] + b12[nt].x) * w22[nt].x
                       + tanhf(c[mt][nt][3] + b12[nt].y) * w22[nt].y;
        }
    #pragma unroll
    for (int off = 1; off < 4; off <<= 1)
        #pragma unroll
        for (int mt = 0; mt < 2; mt++) {
            ps[mt][0] += __shfl_xor_sync(0xffffffffu, ps[mt][0], off);
            ps[mt][1] += __shfl_xor_sync(0xffffffffu, ps[mt][1], off);
        }
    if (tg == 0) {
        float loc = 0.f;
        #pragma unroll
        for (int mt = 0; mt < 2; mt++)
            #pragma unroll
            for (int rh = 0; rh < 2; rh++) {
                int row = row0 + warp_m * 32 + mt * 16 + g + rh * 8;
                if (row < NN) loc += ps[mt][rh];
            }
        atomicAdd(&sacc, loc);
    }
    __syncthreads();
    if (tid == 0) atomicAdd(&g_wsum[r], sacc);
}

// ---------------- semantic softmax ----------------
__global__ void k_softmax(float* __restrict__ out) {
    int t = threadIdx.x;
    if (t < RR) {
        float w0 = g_wsum[0] / (float)NN;
        float w1 = g_wsum[1] / (float)NN;
        float w2 = g_wsum[2] / (float)NN;
        float mx = fmaxf(w0, fmaxf(w1, w2));
        float e0 = expf(w0 - mx), e1 = expf(w1 - mx), e2 = expf(w2 - mx);
        float s = e0 + e1 + e2;
        float a = (t == 0 ? e0 : (t == 1 ? e1 : e2)) / s;
        g_a[t] = a;
        out[(size_t)NN * HD + t] = a;
    }
}

// ---------------- final combine (recompute z_r from acc/ssum/bias) ----------------
__global__ void k_final(const float* __restrict__ bias_g, float* __restrict__ out) {
    int idx = blockIdx.x * blockDim.x + threadIdx.x;
    const int TOT4 = NN * HD / 4;
    if (idx >= TOT4) return;
    float a[RR] = {__ldg(&g_a[0]), __ldg(&g_a[1]), __ldg(&g_a[2])};
    int node = idx >> 5;
    int col0 = (idx & 31) * 4;
    int head = col0 >> 5;
    float4 o = make_float4(0.f, 0.f, 0.f, 0.f);
    #pragma unroll
    for (int r = 0; r < RR; r++) {
        float si = 1.f / (g_ssum[((size_t)r * NN + node) * HH + head] + 1e-9f);
        float4 v = *(const float4*)(g_acc + ((size_t)r * NN + node) * HD + col0);
        float4 bg = *(const float4*)(bias_g + r * HD + col0);
        v.x = v.x * si + bg.x; v.y = v.y * si + bg.y;
        v.z = v.z * si + bg.z; v.w = v.w * si + bg.w;
        v.x = v.x > 0.f ? v.x : expm1f(v.x);
        v.y = v.y > 0.f ? v.y : expm1f(v.y);
        v.z = v.z > 0.f ? v.z : expm1f(v.z);
        v.w = v.w > 0.f ? v.w : expm1f(v.w);
        o.x += a[r] * v.x; o.y += a[r] * v.y;
        o.z += a[r] * v.z; o.w += a[r] * v.w;
    }
    ((float4*)out)[idx] = o;
}

// ---------------- launch ----------------
extern "C" void kernel_launch(void* const* d_in, const int* in_sizes, int n_in,
                              void* d_out, int out_size) {
    const float* dst_feat  = (const float*)d_in[0];
    const float* src_feats = (const float*)d_in[1];
    const int*   src_idx   = (const int*)d_in[2];
    const int*   dst_idx   = (const int*)d_in[3];
    const float* Wt_dst    = (const float*)d_in[4];
    const float* bt_dst    = (const float*)d_in[5];
    const float* Wt_src    = (const float*)d_in[6];
    const float* bt_src    = (const float*)d_in[7];
    const float* Wg        = (const float*)d_in[8];
    const float* attn_l    = (const float*)d_in[9];
    const float* attn_r    = (const float*)d_in[10];
    const float* bias_g    = (const float*)d_in[11];
    const float* W1        = (const float*)d_in[12];
    const float* b1        = (const float*)d_in[13];
    const float* W2        = (const float*)d_in[14];
    float* out = (float*)d_out;

    size_t smem_mma = (size_t)SMEM_FLOATS * sizeof(float);
    cudaFuncSetAttribute(k_gemm_hs_mma, cudaFuncAttributeMaxDynamicSharedMemorySize, (int)smem_mma);
    cudaFuncSetAttribute(k_semantic_mma, cudaFuncAttributeMaxDynamicSharedMemorySize, (int)smem_mma);

    k_init<<<2048, 256>>>();
    k_combine<<<RR * (HIDD + 1), HIDD>>>(Wt_src, bt_src, Wg);
    k_w1t<<<(HD * 128 + 255) / 256, 256>>>(W1);
    k_u<<<(RR * HIDD * HH + 127) / 128, 128>>>(Wg, attn_r);
    k_V<<<(RR * HIDD * HH + 127) / 128, 128>>>(Wt_dst, bt_dst);

    dim3 ggrid((NN + 127) / 128, RR);
    k_gemm_hs_mma<<<ggrid, 256, smem_mma>>>(src_feats, attn_l);
    k_er<<<(NN + 7) / 8, 256>>>(dst_feat);

    int eth = RR * EE;
    k_edge_exp<<<(eth + 255) / 256, 256>>>(src_idx, dst_idx);
    k_scatter<<<(eth * 32 + 255) / 256, 256>>>(src_idx, dst_idx);

    k_semantic_mma<<<ggrid, 256, smem_mma>>>(bias_g, b1, W2);
    k_softmax<<<1, 32>>>(out);
    k_final<<<(NN * HD / 4 + 255) / 256, 256>>>(bias_g, out);
}

// round 5
// speedup vs baseline: 1.7186x; 1.2224x over previous
#include <cuda_runtime.h>
#include <math.h>
#include <stdint.h>

#define NN 100000
#define RR 3
#define EE 320000
#define HIDD 128
#define HH 4
#define HD 128
#define NTOT (RR * NN)

// ---------------- device scratch ----------------
__device__ float g_hs  [(size_t)RR * NN * HD];
__device__ float g_z   [(size_t)RR * NN * HD];   // final elu'd z_r
__device__ float g_el  [(size_t)RR * NN * HH];
__device__ float g_er  [(size_t)RR * NN * HH];
__device__ float g_WcT [RR * HIDD * HD];
__device__ float g_bc  [RR * HD];
__device__ float g_W1T [HD * 128];
__device__ float g_u   [RR * HIDD * HH];
__device__ float g_V   [RR * HIDD * HH];
__device__ float g_c   [RR * HH];
__device__ float g_wsum[RR];
__device__ float g_a   [RR];
// CSR scratch
__device__ int g_deg [NTOT];
__device__ int g_off [NTOT];
__device__ int g_cur [NTOT];
__device__ int g_bsum[512];
__device__ int g_srcs[RR * EE];

// ---------------- helpers ----------------
__device__ __forceinline__ float to_tf32(float x) {
    uint32_t o;
    asm("cvt.rna.tf32.f32 %0, %1;" : "=r"(o) : "f"(x));
    return __uint_as_float(o);
}

#define LDSM4(r0, r1, r2, r3, addr) \
    asm volatile("ldmatrix.sync.aligned.m8n8.x4.shared.b16 {%0,%1,%2,%3}, [%4];" \
                 : "=r"(r0), "=r"(r1), "=r"(r2), "=r"(r3) : "r"(addr))

#define MMA_TF32(c, a, b) \
    asm volatile("mma.sync.aligned.m16n8k8.row.col.f32.tf32.tf32.f32 " \
                 "{%0,%1,%2,%3},{%4,%5,%6,%7},{%8,%9},{%0,%1,%2,%3};" \
                 : "+f"((c)[0]), "+f"((c)[1]), "+f"((c)[2]), "+f"((c)[3]) \
                 : "r"((a)[0]), "r"((a)[1]), "r"((a)[2]), "r"((a)[3]), \
                   "r"((b)[0]), "r"((b)[1]))

// ---------------- zero ----------------
__global__ void k_zero() {
    int i = blockIdx.x * blockDim.x + threadIdx.x;
    if (i < NTOT) g_deg[i] = 0;
    if (i < RR) g_wsum[i] = 0.f;
}

// ---------------- CSR build ----------------
__global__ void k_hist(const int* __restrict__ dst_idx) {
    int idx = blockIdx.x * blockDim.x + threadIdx.x;
    if (idx >= RR * EE) return;
    int r = idx / EE;
    atomicAdd(&g_deg[r * NN + dst_idx[idx]], 1);
}

__global__ void k_scan1() {
    __shared__ int ssum[256];
    int t = threadIdx.x;
    int base = blockIdx.x * 1024 + t * 4;
    int v0 = base + 0 < NTOT ? g_deg[base + 0] : 0;
    int v1 = base + 1 < NTOT ? g_deg[base + 1] : 0;
    int v2 = base + 2 < NTOT ? g_deg[base + 2] : 0;
    int v3 = base + 3 < NTOT ? g_deg[base + 3] : 0;
    int tot = v0 + v1 + v2 + v3;
    ssum[t] = tot;
    __syncthreads();
    for (int o = 1; o < 256; o <<= 1) {
        int x = t >= o ? ssum[t - o] : 0;
        __syncthreads();
        ssum[t] += x;
        __syncthreads();
    }
    int ex = ssum[t] - tot;
    if (t == 255) g_bsum[blockIdx.x] = ssum[255];
    if (base + 0 < NTOT) g_off[base + 0] = ex;
    if (base + 1 < NTOT) g_off[base + 1] = ex + v0;
    if (base + 2 < NTOT) g_off[base + 2] = ex + v0 + v1;
    if (base + 3 < NTOT) g_off[base + 3] = ex + v0 + v1 + v2;
}

__global__ void k_scan2() {
    __shared__ int s[512];
    int t = threadIdx.x;
    const int NB = (NTOT + 1023) / 1024;
    int v = t < NB ? g_bsum[t] : 0;
    s[t] = v;
    __syncthreads();
    for (int o = 1; o < 512; o <<= 1) {
        int x = t >= o ? s[t - o] : 0;
        __syncthreads();
        s[t] += x;
        __syncthreads();
    }
    if (t < NB) g_bsum[t] = s[t] - v;
}

__global__ void k_scan3() {
    int i = blockIdx.x * blockDim.x + threadIdx.x;
    if (i >= NTOT) return;
    int o = g_off[i] + g_bsum[i >> 10];
    g_off[i] = o;
    g_cur[i] = o;
}

__global__ void k_fill(const int* __restrict__ src_idx, const int* __restrict__ dst_idx) {
    int idx = blockIdx.x * blockDim.x + threadIdx.x;
    if (idx >= RR * EE) return;
    int r = idx / EE;
    int pos = atomicAdd(&g_cur[r * NN + dst_idx[idx]], 1);
    g_srcs[pos] = src_idx[idx];
}

// ---------------- weight composition ----------------
__global__ void k_combine(const float* __restrict__ Wt_src,
                          const float* __restrict__ bt_src,
                          const float* __restrict__ Wg) {
    int b = blockIdx.x;
    int r = b / (HIDD + 1);
    int i = b % (HIDD + 1);
    int tid = threadIdx.x;
    __shared__ float srow[HIDD];
    const float* Wgr = Wg + (size_t)r * HIDD * HD;
    srow[tid] = (i < HIDD) ? Wt_src[((size_t)r * HIDD + i) * HIDD + tid]
                           : bt_src[r * HIDD + tid];
    __syncthreads();
    float acc = 0.f;
    #pragma unroll 8
    for (int k = 0; k < HIDD; k++) acc += srow[k] * Wgr[k * HD + tid];
    if (i < HIDD) g_WcT[((size_t)r * HIDD + tid) * HIDD + i] = to_tf32(acc);
    else          g_bc[r * HD + tid] = acc;
}

__global__ void k_w1t(const float* __restrict__ W1) {
    int idx = blockIdx.x * blockDim.x + threadIdx.x;
    if (idx >= HD * 128) return;
    int n = idx / 128, k = idx % 128;
    g_W1T[n * 128 + k] = to_tf32(W1[k * 128 + n]);
}

__global__ void k_u(const float* __restrict__ Wg, const float* __restrict__ attn_r) {
    int idx = blockIdx.x * blockDim.x + threadIdx.x;
    if (idx >= RR * HIDD * HH) return;
    int r = idx / (HIDD * HH);
    int rem = idx % (HIDD * HH);
    int k = rem / HH, h = rem % HH;
    const float* wg = Wg + (size_t)r * HIDD * HD + k * HD + h * 32;
    const float* ar = attn_r + r * HD + h * 32;
    float s = 0.f;
    #pragma unroll
    for (int d = 0; d < 32; d++) s += wg[d] * ar[d];
    g_u[idx] = s;
}

__global__ void k_V(const float* __restrict__ Wt_dst, const float* __restrict__ bt_dst) {
    int idx = blockIdx.x * blockDim.x + threadIdx.x;
    if (idx >= RR * HIDD * HH) return;
    int r = idx / (HIDD * HH);
    int rem = idx % (HIDD * HH);
    int f = rem / HH, h = rem % HH;
    const float* u = g_u + r * HIDD * HH;
    float s = 0.f;
    for (int k = 0; k < HIDD; k++) s += Wt_dst[f * HIDD + k] * u[k * HH + h];
    g_V[idx] = s;
    if (f == 0) {
        float c = 0.f;
        for (int k = 0; k < HIDD; k++) c += bt_dst[k] * u[k * HH + h];
        g_c[r * HH + h] = c;
    }
}

// ---------------- TF32 MMA GEMM geometry ----------------
constexpr int AS_STR = 20;
constexpr int WS_STR = 132;
constexpr int AS_BUF = 128 * AS_STR;
constexpr int SMEM_FLOATS = 128 * WS_STR + 2 * AS_BUF;

// ---------------- hs GEMM: g_hs = A @ Wc + bc, el epilogue ----------------
__global__ __launch_bounds__(256) void k_gemm_hs_mma(const float* __restrict__ src_feats,
                                                     const float* __restrict__ attn_l) {
    extern __shared__ float sm[];
    float* Ws = sm;
    float* As = sm + 128 * WS_STR;
    int tid = threadIdx.x;
    int r = blockIdx.y;
    int row0 = blockIdx.x * 128;
    const float* A = src_feats + (size_t)r * NN * HIDD;

    const float4* Wt4 = (const float4*)(g_WcT + (size_t)r * HIDD * HD);
    #pragma unroll
    for (int i = 0; i < 16; i++) {
        int idx = tid + i * 256;
        int n = idx >> 5, kq = idx & 31;
        *(float4*)(Ws + n * WS_STR + kq * 4) = Wt4[idx];
    }

    int grow = row0 + (tid >> 1);
    int koffA = (tid & 1) * 8;
    float4 areg0, areg1;
    float4 z4 = make_float4(0.f, 0.f, 0.f, 0.f);

    uint32_t sbase = (uint32_t)__cvta_generic_to_shared(sm);
    uint32_t asbase = sbase + 128 * WS_STR * 4;

    int lane = tid & 31, warp = tid >> 5;
    int warp_m = warp >> 1, warp_n = warp & 1;
    int n0 = warp_n * 64;
    int g = lane >> 2, tg = lane & 3;
    int grp = lane >> 3, rin = lane & 7;
    int arow = (grp & 1) * 8 + rin;
    int akoff = (grp >> 1) * 4;
    int brow = (grp >> 1) * 8 + rin;
    int bkoff = (grp & 1) * 4;

    uint32_t aAddr[2], bAddr[4];
    #pragma unroll
    for (int mt = 0; mt < 2; mt++)
        aAddr[mt] = asbase + ((warp_m * 32 + mt * 16 + arow) * AS_STR + akoff) * 4;
    #pragma unroll
    for (int pi = 0; pi < 4; pi++)
        bAddr[pi] = sbase + ((n0 + pi * 16 + brow) * WS_STR + bkoff) * 4;

    float c[2][8][4];
    #pragma unroll
    for (int mt = 0; mt < 2; mt++)
        #pragma unroll
        for (int nt = 0; nt < 8; nt++)
            #pragma unroll
            for (int q = 0; q < 4; q++) c[mt][nt][q] = 0.f;

    if (grow < NN) {
        const float4* p = (const float4*)(A + (size_t)grow * HIDD + koffA);
        areg0 = p[0]; areg1 = p[1];
    } else { areg0 = z4; areg1 = z4; }

    for (int kb = 0; kb < 8; kb++) {
        {
            float* dst = As + (kb & 1) * AS_BUF + (tid >> 1) * AS_STR + koffA;
            dst[0] = to_tf32(areg0.x); dst[1] = to_tf32(areg0.y);
            dst[2] = to_tf32(areg0.z); dst[3] = to_tf32(areg0.w);
            dst[4] = to_tf32(areg1.x); dst[5] = to_tf32(areg1.y);
            dst[6] = to_tf32(areg1.z); dst[7] = to_tf32(areg1.w);
        }
        if (kb < 7) {
            if (grow < NN) {
                const float4* p = (const float4*)(A + (size_t)grow * HIDD + (kb + 1) * 16 + koffA);
                areg0 = p[0]; areg1 = p[1];
            } else { areg0 = z4; areg1 = z4; }
        }
        __syncthreads();
        uint32_t abufoff = (kb & 1) * AS_BUF * 4;
        #pragma unroll
        for (int k8 = 0; k8 < 2; k8++) {
            uint32_t a[2][4], b[8][2];
            #pragma unroll
            for (int mt = 0; mt < 2; mt++)
                LDSM4(a[mt][0], a[mt][1], a[mt][2], a[mt][3],
                      aAddr[mt] + abufoff + k8 * 32);
            #pragma unroll
            for (int pi = 0; pi < 4; pi++)
                LDSM4(b[2 * pi][0], b[2 * pi][1], b[2 * pi + 1][0], b[2 * pi + 1][1],
                      bAddr[pi] + (kb * 16 + k8 * 8) * 4);
            #pragma unroll
            for (int mt = 0; mt < 2; mt++)
                #pragma unroll
                for (int nt = 0; nt < 8; nt++)
                    MMA_TF32(c[mt][nt], a[mt], b[nt]);
        }
    }

    float2 bc2[8], al2[8];
    #pragma unroll
    for (int nt = 0; nt < 8; nt++) {
        bc2[nt] = *(const float2*)(g_bc + r * HD + n0 + nt * 8 + 2 * tg);
        al2[nt] = *(const float2*)(attn_l + r * HD + n0 + nt * 8 + 2 * tg);
    }
    float elp[2][2][2];
    #pragma unroll
    for (int mt = 0; mt < 2; mt++)
        #pragma unroll
        for (int rh = 0; rh < 2; rh++) { elp[mt][rh][0] = 0.f; elp[mt][rh][1] = 0.f; }

    #pragma unroll
    for (int mt = 0; mt < 2; mt++) {
        int rowa = row0 + warp_m * 32 + mt * 16 + g;
        #pragma unroll
        for (int nt = 0; nt < 8; nt++) {
            float c0 = c[mt][nt][0] + bc2[nt].x, c1 = c[mt][nt][1] + bc2[nt].y;
            float c2 = c[mt][nt][2] + bc2[nt].x, c3 = c[mt][nt][3] + bc2[nt].y;
            int h = nt >> 2;
            elp[mt][0][h] += c0 * al2[nt].x + c1 * al2[nt].y;
            elp[mt][1][h] += c2 * al2[nt].x + c3 * al2[nt].y;
            if (rowa < NN)
                *(float2*)(g_hs + ((size_t)r * NN + rowa) * HD + n0 + nt * 8 + 2 * tg) = make_float2(c0, c1);
            if (rowa + 8 < NN)
                *(float2*)(g_hs + ((size_t)r * NN + rowa + 8) * HD + n0 + nt * 8 + 2 * tg) = make_float2(c2, c3);
        }
    }
    #pragma unroll
    for (int off = 1; off < 4; off <<= 1)
        #pragma unroll
        for (int mt = 0; mt < 2; mt++)
            #pragma unroll
            for (int rh = 0; rh < 2; rh++) {
                elp[mt][rh][0] += __shfl_xor_sync(0xffffffffu, elp[mt][rh][0], off);
                elp[mt][rh][1] += __shfl_xor_sync(0xffffffffu, elp[mt][rh][1], off);
            }
    if (tg == 0) {
        #pragma unroll
        for (int mt = 0; mt < 2; mt++)
            #pragma unroll
            for (int rh = 0; rh < 2; rh++) {
                int row = row0 + warp_m * 32 + mt * 16 + g + rh * 8;
                if (row < NN) {
                    g_el[((size_t)r * NN + row) * HH + warp_n * 2 + 0] = elp[mt][rh][0];
                    g_el[((size_t)r * NN + row) * HH + warp_n * 2 + 1] = elp[mt][rh][1];
                }
            }
    }
}

// ---------------- er: dst_feat @ V ----------------
__global__ void k_er(const float* __restrict__ dst_feat) {
    __shared__ float sV[RR * HIDD * HH];
    __shared__ float sc[RR * HH];
    int tid = threadIdx.x;
    for (int i = tid; i < RR * HIDD * HH; i += blockDim.x) sV[i] = g_V[i];
    if (tid < RR * HH) sc[tid] = g_c[tid];
    __syncthreads();
    int node = blockIdx.x * 8 + (tid >> 5);
    int lane = tid & 31;
    if (node >= NN) return;
    float4 f = ((const float4*)dst_feat)[(size_t)node * 32 + lane];
    #pragma unroll
    for (int r = 0; r < RR; r++) {
        const float* base = sV + r * HIDD * HH;
        float4 v0 = *(const float4*)(base + (lane * 4 + 0) * 4);
        float4 v1 = *(const float4*)(base + (lane * 4 + 1) * 4);
        float4 v2 = *(const float4*)(base + (lane * 4 + 2) * 4);
        float4 v3 = *(const float4*)(base + (lane * 4 + 3) * 4);
        float p0 = f.x * v0.x + f.y * v1.x + f.z * v2.x + f.w * v3.x;
        float p1 = f.x * v0.y + f.y * v1.y + f.z * v2.y + f.w * v3.y;
        float p2 = f.x * v0.z + f.y * v1.z + f.z * v2.z + f.w * v3.z;
        float p3 = f.x * v0.w + f.y * v1.w + f.z * v2.w + f.w * v3.w;
        #pragma unroll
        for (int off = 16; off; off >>= 1) {
            p0 += __shfl_xor_sync(0xffffffffu, p0, off);
            p1 += __shfl_xor_sync(0xffffffffu, p1, off);
            p2 += __shfl_xor_sync(0xffffffffu, p2, off);
            p3 += __shfl_xor_sync(0xffffffffu, p3, off);
        }
        if (lane == 0) {
            float* erp = g_er + ((size_t)r * NN + node) * HH;
            erp[0] = p0 + sc[r * HH + 0];
            erp[1] = p1 + sc[r * HH + 1];
            erp[2] = p2 + sc[r * HH + 2];
            erp[3] = p3 + sc[r * HH + 3];
        }
    }
}

// ---------------- pull-based aggregation: warp per (r,dst), atomic-free ----------------
__global__ __launch_bounds__(256) void k_gather(const float* __restrict__ bias_g) {
    int w = (blockIdx.x * 256 + threadIdx.x) >> 5;
    int lane = threadIdx.x & 31;
    if (w >= NTOT) return;
    int r = w / NN;
    int off = g_off[w], deg = g_deg[w];
    int h = lane >> 3;
    float er = g_er[(size_t)w * HH + h];
    float a0 = 0.f, a1 = 0.f, a2 = 0.f, a3 = 0.f, ss = 0.f;
    for (int j = 0; j < deg; j++) {
        int s = g_srcs[off + j];
        float el = __ldg(&g_el[((size_t)r * NN + s) * HH + h]);
        float e = el + er;
        e = e > 0.f ? e : 0.2f * e;
        float ex = expf(e);
        float4 hv = *(const float4*)(g_hs + ((size_t)r * NN + s) * HD + lane * 4);
        a0 += ex * hv.x; a1 += ex * hv.y; a2 += ex * hv.z; a3 += ex * hv.w;
        ss += ex;
    }
    float si = 1.f / (ss + 1e-9f);
    float4 bg = *(const float4*)(bias_g + r * HD + lane * 4);
    float z0 = a0 * si + bg.x, z1 = a1 * si + bg.y;
    float z2 = a2 * si + bg.z, z3 = a3 * si + bg.w;
    z0 = z0 > 0.f ? z0 : expm1f(z0);
    z1 = z1 > 0.f ? z1 : expm1f(z1);
    z2 = z2 > 0.f ? z2 : expm1f(z2);
    z3 = z3 > 0.f ? z3 : expm1f(z3);
    *(float4*)(g_z + (size_t)w * HD + lane * 4) = make_float4(z0, z1, z2, z3);
}

// ---------------- semantic GEMM: reads elu'd z directly ----------------
__global__ __launch_bounds__(256) void k_semantic_mma(const float* __restrict__ b1,
                                                      const float* __restrict__ W2) {
    extern __shared__ float sm[];
    float* Ws = sm;
    float* As = sm + 128 * WS_STR;
    __shared__ float sacc;
    int tid = threadIdx.x;
    if (tid == 0) sacc = 0.f;
    int r = blockIdx.y;
    int row0 = blockIdx.x * 128;
    const float* A = g_z + (size_t)r * NN * HD;

    const float4* Wt4 = (const float4*)g_W1T;
    #pragma unroll
    for (int i = 0; i < 16; i++) {
        int idx = tid + i * 256;
        int n = idx >> 5, kq = idx & 31;
        *(float4*)(Ws + n * WS_STR + kq * 4) = Wt4[idx];
    }

    int grow = row0 + (tid >> 1);
    int koffA = (tid & 1) * 8;
    float4 areg0, areg1;
    float4 z4 = make_float4(0.f, 0.f, 0.f, 0.f);

    uint32_t sbase = (uint32_t)__cvta_generic_to_shared(sm);
    uint32_t asbase = sbase + 128 * WS_STR * 4;

    int lane = tid & 31, warp = tid >> 5;
    int warp_m = warp >> 1, warp_n = warp & 1;
    int n0 = warp_n * 64;
    int g = lane >> 2, tg = lane & 3;
    int grp = lane >> 3, rin = lane & 7;
    int arow = (grp & 1) * 8 + rin;
    int akoff = (grp >> 1) * 4;
    int brow = (grp >> 1) * 8 + rin;
    int bkoff = (grp & 1) * 4;

    uint32_t aAddr[2], bAddr[4];
    #pragma unroll
    for (int mt = 0; mt < 2; mt++)
        aAddr[mt] = asbase + ((warp_m * 32 + mt * 16 + arow) * AS_STR + akoff) * 4;
    #pragma unroll
    for (int pi = 0; pi < 4; pi++)
        bAddr[pi] = sbase + ((n0 + pi * 16 + brow) * WS_STR + bkoff) * 4;

    float c[2][8][4];
    #pragma unroll
    for (int mt = 0; mt < 2; mt++)
        #pragma unroll
        for (int nt = 0; nt < 8; nt++)
            #pragma unroll
            for (int q = 0; q < 4; q++) c[mt][nt][q] = 0.f;

    if (grow < NN) {
        const float4* p = (const float4*)(A + (size_t)grow * HD + koffA);
        areg0 = p[0]; areg1 = p[1];
    } else { areg0 = z4; areg1 = z4; }

    for (int kb = 0; kb < 8; kb++) {
        {
            float* dst = As + (kb & 1) * AS_BUF + (tid >> 1) * AS_STR + koffA;
            dst[0] = to_tf32(areg0.x); dst[1] = to_tf32(areg0.y);
            dst[2] = to_tf32(areg0.z); dst[3] = to_tf32(areg0.w);
            dst[4] = to_tf32(areg1.x); dst[5] = to_tf32(areg1.y);
            dst[6] = to_tf32(areg1.z); dst[7] = to_tf32(areg1.w);
        }
        if (kb < 7) {
            if (grow < NN) {
                const float4* p = (const float4*)(A + (size_t)grow * HD + (kb + 1) * 16 + koffA);
                areg0 = p[0]; areg1 = p[1];
            } else { areg0 = z4; areg1 = z4; }
        }
        __syncthreads();
        uint32_t abufoff = (kb & 1) * AS_BUF * 4;
        #pragma unroll
        for (int k8 = 0; k8 < 2; k8++) {
            uint32_t a[2][4], b[8][2];
            #pragma unroll
            for (int mt = 0; mt < 2; mt++)
                LDSM4(a[mt][0], a[mt][1], a[mt][2], a[mt][3],
                      aAddr[mt] + abufoff + k8 * 32);
            #pragma unroll
            for (int pi = 0; pi < 4; pi++)
                LDSM4(b[2 * pi][0], b[2 * pi][1], b[2 * pi + 1][0], b[2 * pi + 1][1],
                      bAddr[pi] + (kb * 16 + k8 * 8) * 4);
            #pragma unroll
            for (int mt = 0; mt < 2; mt++)
                #pragma unroll
                for (int nt = 0; nt < 8; nt++)
                    MMA_TF32(c[mt][nt], a[mt], b[nt]);
        }
    }

    float2 b12[8], w22[8];
    #pragma unroll
    for (int nt = 0; nt < 8; nt++) {
        b12[nt] = *(const float2*)(b1 + n0 + nt * 8 + 2 * tg);
        w22[nt] = *(const float2*)(W2 + n0 + nt * 8 + 2 * tg);
    }
    float ps[2][2] = {{0.f, 0.f}, {0.f, 0.f}};
    #pragma unroll
    for (int mt = 0; mt < 2; mt++)
        #pragma unroll
        for (int nt = 0; nt < 8; nt++) {
            ps[mt][0] += tanhf(c[mt][nt][0] + b12[nt].x) * w22[nt].x
                       + tanhf(c[mt][nt][1] + b12[nt].y) * w22[nt].y;
            ps[mt][1] += tanhf(c[mt][nt][2] + b12[nt].x) * w22[nt].x
                       + tanhf(c[mt][nt][3] + b12[nt].y) * w22[nt].y;
        }
    #pragma unroll
    for (int off = 1; off < 4; off <<= 1)
        #pragma unroll
        for (int mt = 0; mt < 2; mt++) {
            ps[mt][0] += __shfl_xor_sync(0xffffffffu, ps[mt][0], off);
            ps[mt][1] += __shfl_xor_sync(0xffffffffu, ps[mt][1], off);
        }
    if (tg == 0) {
        float loc = 0.f;
        #pragma unroll
        for (int mt = 0; mt < 2; mt++)
            #pragma unroll
            for (int rh = 0; rh < 2; rh++) {
                int row = row0 + warp_m * 32 + mt * 16 + g + rh * 8;
                if (row < NN) loc += ps[mt][rh];
            }
        atomicAdd(&sacc, loc);
    }
    __syncthreads();
    if (tid == 0) atomicAdd(&g_wsum[r], sacc);
}

// ---------------- semantic softmax ----------------
__global__ void k_softmax(float* __restrict__ out) {
    int t = threadIdx.x;
    if (t < RR) {
        float w0 = g_wsum[0] / (float)NN;
        float w1 = g_wsum[1] / (float)NN;
        float w2 = g_wsum[2] / (float)NN;
        float mx = fmaxf(w0, fmaxf(w1, w2));
        float e0 = expf(w0 - mx), e1 = expf(w1 - mx), e2 = expf(w2 - mx);
        float s = e0 + e1 + e2;
        float a = (t == 0 ? e0 : (t == 1 ? e1 : e2)) / s;
        g_a[t] = a;
        out[(size_t)NN * HD + t] = a;
    }
}

// ---------------- final combine ----------------
__global__ void k_final(float* __restrict__ out) {
    int idx = blockIdx.x * blockDim.x + threadIdx.x;
    const int TOT4 = NN * HD / 4;
    if (idx >= TOT4) return;
    float a0 = __ldg(&g_a[0]), a1 = __ldg(&g_a[1]), a2 = __ldg(&g_a[2]);
    const float4* z = (const float4*)g_z;
    float4 z0 = z[idx], z1 = z[idx + TOT4], z2 = z[idx + 2 * TOT4];
    float4 o;
    o.x = a0 * z0.x + a1 * z1.x + a2 * z2.x;
    o.y = a0 * z0.y + a1 * z1.y + a2 * z2.y;
    o.z = a0 * z0.z + a1 * z1.z + a2 * z2.z;
    o.w = a0 * z0.w + a1 * z1.w + a2 * z2.w;
    ((float4*)out)[idx] = o;
}

// ---------------- launch ----------------
extern "C" void kernel_launch(void* const* d_in, const int* in_sizes, int n_in,
                              void* d_out, int out_size) {
    const float* dst_feat  = (const float*)d_in[0];
    const float* src_feats = (const float*)d_in[1];
    const int*   src_idx   = (const int*)d_in[2];
    const int*   dst_idx   = (const int*)d_in[3];
    const float* Wt_dst    = (const float*)d_in[4];
    const float* bt_dst    = (const float*)d_in[5];
    const float* Wt_src    = (const float*)d_in[6];
    const float* bt_src    = (const float*)d_in[7];
    const float* Wg        = (const float*)d_in[8];
    const float* attn_l    = (const float*)d_in[9];
    const float* attn_r    = (const float*)d_in[10];
    const float* bias_g    = (const float*)d_in[11];
    const float* W1        = (const float*)d_in[12];
    const float* b1        = (const float*)d_in[13];
    const float* W2        = (const float*)d_in[14];
    float* out = (float*)d_out;

    size_t smem_mma = (size_t)SMEM_FLOATS * sizeof(float);
    cudaFuncSetAttribute(k_gemm_hs_mma, cudaFuncAttributeMaxDynamicSharedMemorySize, (int)smem_mma);
    cudaFuncSetAttribute(k_semantic_mma, cudaFuncAttributeMaxDynamicSharedMemorySize, (int)smem_mma);

    int eth = RR * EE;
    k_zero<<<(NTOT + 255) / 256, 256>>>();
    k_combine<<<RR * (HIDD + 1), HIDD>>>(Wt_src, bt_src, Wg);
    k_w1t<<<(HD * 128 + 255) / 256, 256>>>(W1);
    k_u<<<(RR * HIDD * HH + 127) / 128, 128>>>(Wg, attn_r);
    k_V<<<(RR * HIDD * HH + 127) / 128, 128>>>(Wt_dst, bt_dst);

    // CSR build (independent of GEMMs)
    k_hist<<<(eth + 255) / 256, 256>>>(dst_idx);
    k_scan1<<<(NTOT + 1023) / 1024, 256>>>();
    k_scan2<<<1, 512>>>();
    k_scan3<<<(NTOT + 255) / 256, 256>>>();
    k_fill<<<(eth + 255) / 256, 256>>>(src_idx, dst_idx);

    dim3 ggrid((NN + 127) / 128, RR);
    k_gemm_hs_mma<<<ggrid, 256, smem_mma>>>(src_feats, attn_l);
    k_er<<<(NN + 7) / 8, 256>>>(dst_feat);

    k_gather<<<(NTOT * 32 + 255) / 256, 256>>>(bias_g);

    k_semantic_mma<<<ggrid, 256, smem_mma>>>(b1, W2);
    k_softmax<<<1, 32>>>(out);
    k_final<<<(NN * HD / 4 + 255) / 256, 256>>>(out);
}